// round 9
// baseline (speedup 1.0000x reference)
#include <cuda_runtime.h>
#include <cuda_fp16.h>
#include <cstdint>

#define THREADS     256
#define FDIM        256
#define N_GEMM      24          // z1 = tanh(c), then 24 GEMM iterations (25 total)
#define N_PAIRS     1024        // 32768 rows / 32 rows per tile-pair

#define ROW_BYTES   512                          // 256 halfs per row
#define W_BYTES     (FDIM * ROW_BYTES)           // 131072
#define ZT_BYTES    (16 * ROW_BYTES)             // 8192 per 16-row z buffer
#define OFF_ZA0     W_BYTES
#define OFF_ZA1     (W_BYTES + ZT_BYTES)
#define OFF_ZB0     (W_BYTES + 2 * ZT_BYTES)
#define OFF_ZB1     (W_BYTES + 3 * ZT_BYTES)
#define SMEM_BYTES  (W_BYTES + 4 * ZT_BYTES)     // 163840 (160 KB)

static __device__ __forceinline__ uint32_t smem_u32(const void* p) {
    uint32_t a;
    asm("{ .reg .u64 t; cvta.to.shared.u64 t, %1; cvt.u32.u64 %0, t; }" : "=r"(a) : "l"(p));
    return a;
}

// Byte offset of half element (r, k) in a swizzled [rows x 256] fp16 tile.
static __device__ __forceinline__ uint32_t swz(uint32_t r, uint32_t k) {
    return r * ROW_BYTES + (((k >> 3) ^ (r & 7)) << 4) + ((k & 7) << 1);
}

static __device__ __forceinline__ void ldsm4(uint32_t r[4], uint32_t addr) {
    asm volatile("ldmatrix.sync.aligned.m8n8.x4.shared.b16 {%0,%1,%2,%3}, [%4];"
                 : "=r"(r[0]), "=r"(r[1]), "=r"(r[2]), "=r"(r[3]) : "r"(addr));
}

static __device__ __forceinline__ void mma16816(float d[4], const uint32_t a[4],
                                                uint32_t b0, uint32_t b1) {
    asm volatile("mma.sync.aligned.m16n8k16.row.col.f32.f16.f16.f32 "
                 "{%0,%1,%2,%3}, {%4,%5,%6,%7}, {%8,%9}, {%0,%1,%2,%3};"
                 : "+f"(d[0]), "+f"(d[1]), "+f"(d[2]), "+f"(d[3])
                 : "r"(a[0]), "r"(a[1]), "r"(a[2]), "r"(a[3]), "r"(b0), "r"(b1));
}

static __device__ __forceinline__ float tanh_fast(float x) {
    float y;
    asm("tanh.approx.f32 %0, %1;" : "=f"(y) : "f"(x));
    return y;
}

// Accurate final-iteration tanh: 1 - 2/(1 + e^{2x}), ~1e-6 rel error.
static __device__ __forceinline__ float tanh_acc(float x) {
    float e, r;
    asm("ex2.approx.f32 %0, %1;" : "=f"(e) : "f"(x * 2.8853900817779268f));
    asm("rcp.approx.f32 %0, %1;" : "=f"(r) : "f"(1.0f + e));
    return 1.0f - 2.0f * r;
}

// Store a 16-row tile's activations (fast tanh) into a z buffer (n32 slice).
static __device__ __forceinline__ void epi_store(
    char* smem, uint32_t zoff, const float v[4][4], int qr, int wn, int qc)
{
#pragma unroll
    for (int nf = 0; nf < 4; ++nf) {
        int c0 = wn + nf * 8 + qc;
        __half2 h0 = __floats2half2_rn(tanh_fast(v[nf][0]), tanh_fast(v[nf][1]));
        __half2 h1 = __floats2half2_rn(tanh_fast(v[nf][2]), tanh_fast(v[nf][3]));
        *reinterpret_cast<__half2*>(smem + zoff + swz(qr,     c0)) = h0;
        *reinterpret_cast<__half2*>(smem + zoff + swz(qr + 8, c0)) = h1;
    }
}

// Final-iteration epilogue: accurate tanh, fp32 straight to gmem.
static __device__ __forceinline__ void epi_final(
    float* __restrict__ out, int rbase, const float v[4][4], int qr, int wn, int qc)
{
#pragma unroll
    for (int nf = 0; nf < 4; ++nf) {
        int rg = rbase + qr;
        int c0 = wn + nf * 8 + qc;
        float2 v0 = make_float2(tanh_acc(v[nf][0]), tanh_acc(v[nf][1]));
        float2 v1 = make_float2(tanh_acc(v[nf][2]), tanh_acc(v[nf][3]));
        *reinterpret_cast<float2*>(out + (size_t)rg * FDIM + c0)       = v0;
        *reinterpret_cast<float2*>(out + (size_t)(rg + 8) * FDIM + c0) = v1;
    }
}

__global__ void __launch_bounds__(THREADS, 1)
fixed_point_kernel(const float* __restrict__ x, const float* __restrict__ W,
                   const float* __restrict__ b, float* __restrict__ out)
{
    extern __shared__ char smem[];
    const uint32_t sb = smem_u32(smem);
    const uint32_t Wb = sb;

    const int tid = threadIdx.x;
    const int wid = tid >> 5;
    const int l   = tid & 31;
    const int wn  = wid << 5;                 // this warp's 32-col slice of N=256
    const int qr  = l >> 2;
    const int qc  = (l & 3) << 1;

    // ---- One-time: W -> SMEM fp16 swizzled [n][k] ----
    for (int idx = tid; idx < FDIM * (FDIM / 4); idx += THREADS) {
        int n  = idx >> 6;
        int k4 = (idx & 63) << 2;
        float4 wv = *reinterpret_cast<const float4*>(W + n * FDIM + k4);
        __half2 h0 = __floats2half2_rn(wv.x, wv.y);
        __half2 h1 = __floats2half2_rn(wv.z, wv.w);
        uint2 v;
        v.x = *reinterpret_cast<uint32_t*>(&h0);
        v.y = *reinterpret_cast<uint32_t*>(&h1);
        *reinterpret_cast<uint2*>(smem + swz(n, k4)) = v;
    }
    __syncthreads();

    // ---- One-time: B fragments (whole K, n32 slice) -> 128 registers ----
    const uint32_t b_r = (uint32_t)(wn + ((l >> 4) & 1) * 8 + (l & 7));
    const uint32_t b_k = (uint32_t)(((l >> 3) & 1) * 8);
    uint32_t Breg[128];
#pragma unroll
    for (int ks = 0; ks < 16; ++ks) {
        ldsm4(&Breg[ks * 8],     Wb + swz(b_r,      ks * 16 + b_k));
        ldsm4(&Breg[ks * 8 + 4], Wb + swz(b_r + 16, ks * 16 + b_k));
    }

    // ---- One-time: bias values for this thread's output columns ----
    float bias[4][2];
#pragma unroll
    for (int nf = 0; nf < 4; ++nf) {
        float2 bv = *reinterpret_cast<const float2*>(b + wn + nf * 8 + qc);
        bias[nf][0] = bv.x;
        bias[nf][1] = bv.y;
    }

    const uint32_t a_r = (uint32_t)(((l >> 3) & 1) * 8 + (l & 7));
    const uint32_t a_k = (uint32_t)(((l >> 4) & 1) * 8);
    const uint32_t ZA0 = sb + OFF_ZA0, ZA1 = sb + OFF_ZA1;
    const uint32_t ZB0 = sb + OFF_ZB0, ZB1 = sb + OFF_ZB1;

    // ---- Persistent loop over 32-row tile pairs ----
    for (int pair = blockIdx.x; pair < N_PAIRS; pair += gridDim.x) {
        const int row0 = pair * 32;           // tile A rows [row0,row0+16), B next 16

        // c = x + b fragments for both 16-row tiles
        float cA[4][4], cB[4][4];
#pragma unroll
        for (int half = 0; half < 2; ++half) {
            int rA = row0 + qr + half * 8;
            const float* xrA = x + (size_t)rA * FDIM;
            const float* xrB = xrA + 16 * FDIM;
#pragma unroll
            for (int nf = 0; nf < 4; ++nf) {
                int c0 = wn + nf * 8 + qc;
                float2 xa = *reinterpret_cast<const float2*>(xrA + c0);
                float2 xb = *reinterpret_cast<const float2*>(xrB + c0);
                cA[nf][half * 2 + 0] = xa.x + bias[nf][0];
                cA[nf][half * 2 + 1] = xa.y + bias[nf][1];
                cB[nf][half * 2 + 0] = xb.x + bias[nf][0];
                cB[nf][half * 2 + 1] = xb.y + bias[nf][1];
            }
        }

        // Iteration 0: z1 = tanh(c) -> ping buffers
        epi_store(smem, OFF_ZA0, cA, qr, wn, qc);
        epi_store(smem, OFF_ZB0, cB, qr, wn, qc);
        __syncthreads();

        // Iterations 1..23 (ping-pong z buffers, ONE barrier per iteration)
        float accA[4][4], accB[4][4];
#pragma unroll 1
        for (int it = 1; it < N_GEMM; ++it) {
            const bool odd = (it & 1) != 0;
            const uint32_t ZAsrc = odd ? ZA0 : ZA1;
            const uint32_t ZBsrc = odd ? ZB0 : ZB1;
            const uint32_t zAdst = odd ? OFF_ZA1 : OFF_ZA0;
            const uint32_t zBdst = odd ? OFF_ZB1 : OFF_ZB0;

#pragma unroll
            for (int nf = 0; nf < 4; ++nf)
#pragma unroll
                for (int j = 0; j < 4; ++j) {
                    accA[nf][j] = cA[nf][j];
                    accB[nf][j] = cB[nf][j];
                }

            // Interleaved dual-tile GEMM: 2 ldsm + 8 independent-acc MMAs per k-step.
#pragma unroll
            for (int ks = 0; ks < 16; ++ks) {
                uint32_t aA[4], aB[4];
                ldsm4(aA, ZAsrc + swz(a_r, ks * 16 + a_k));
                ldsm4(aB, ZBsrc + swz(a_r, ks * 16 + a_k));
                const uint32_t* Bk = &Breg[ks * 8];
                mma16816(accA[0], aA, Bk[0], Bk[1]);
                mma16816(accA[1], aA, Bk[2], Bk[3]);
                mma16816(accB[0], aB, Bk[0], Bk[1]);
                mma16816(accB[1], aB, Bk[2], Bk[3]);
                mma16816(accA[2], aA, Bk[4], Bk[5]);
                mma16816(accA[3], aA, Bk[6], Bk[7]);
                mma16816(accB[2], aB, Bk[4], Bk[5]);
                mma16816(accB[3], aB, Bk[6], Bk[7]);
            }

            epi_store(smem, zAdst, accA, qr, wn, qc);
            epi_store(smem, zBdst, accB, qr, wn, qc);
            __syncthreads();
        }

        // Final iteration (it = 24, sources are pong buffers ZA1/ZB1)
#pragma unroll
        for (int nf = 0; nf < 4; ++nf)
#pragma unroll
            for (int j = 0; j < 4; ++j) {
                accA[nf][j] = cA[nf][j];
                accB[nf][j] = cB[nf][j];
            }
#pragma unroll
        for (int ks = 0; ks < 16; ++ks) {
            uint32_t aA[4], aB[4];
            ldsm4(aA, ZA1 + swz(a_r, ks * 16 + a_k));
            ldsm4(aB, ZB1 + swz(a_r, ks * 16 + a_k));
            const uint32_t* Bk = &Breg[ks * 8];
            mma16816(accA[0], aA, Bk[0], Bk[1]);
            mma16816(accA[1], aA, Bk[2], Bk[3]);
            mma16816(accB[0], aB, Bk[0], Bk[1]);
            mma16816(accB[1], aB, Bk[2], Bk[3]);
            mma16816(accA[2], aA, Bk[4], Bk[5]);
            mma16816(accA[3], aA, Bk[6], Bk[7]);
            mma16816(accB[2], aB, Bk[4], Bk[5]);
            mma16816(accB[3], aB, Bk[6], Bk[7]);
        }
        epi_final(out, row0,      accA, qr, wn, qc);
        epi_final(out, row0 + 16, accB, qr, wn, qc);
        __syncthreads();   // z buffers safe for next pair's iteration 0
    }
}

extern "C" void kernel_launch(void* const* d_in, const int* in_sizes, int n_in,
                              void* d_out, int out_size)
{
    (void)in_sizes; (void)n_in; (void)out_size;
    const float* x = (const float*)d_in[0];
    const float* W = (const float*)d_in[1];
    const float* b = (const float*)d_in[2];
    float* out = (float*)d_out;

    int dev = 0, sms = 0;
    cudaGetDevice(&dev);
    cudaDeviceGetAttribute(&sms, cudaDevAttrMultiProcessorCount, dev);
    int grid = sms > 0 ? sms : 128;
    if (grid > N_PAIRS) grid = N_PAIRS;

    cudaFuncSetAttribute(fixed_point_kernel, cudaFuncAttributeMaxDynamicSharedMemorySize, SMEM_BYTES);
    fixed_point_kernel<<<grid, THREADS, SMEM_BYTES>>>(x, W, b, out);
}

// round 10
// speedup vs baseline: 1.5431x; 1.5431x over previous
#include <cuda_runtime.h>
#include <cuda_fp16.h>
#include <cstdint>

#define THREADS     512
#define FDIM        256
#define N_GEMM      24          // z1 = tanh(c), then 24 GEMM iterations (25 total)
#define N_PAIRS     1024        // 32768 rows / 32 rows per tile-pair

#define ROW_BYTES   512                          // 256 halfs per row
#define W_BYTES     (FDIM * ROW_BYTES)           // 131072
#define ZT_BYTES    (16 * ROW_BYTES)             // 8192 per 16-row z buffer
#define OFF_ZA0     W_BYTES
#define OFF_ZA1     (W_BYTES + ZT_BYTES)
#define OFF_ZB0     (W_BYTES + 2 * ZT_BYTES)
#define OFF_ZB1     (W_BYTES + 3 * ZT_BYTES)
#define SMEM_BYTES  (W_BYTES + 4 * ZT_BYTES)     // 163840 (160 KB)

static __device__ __forceinline__ uint32_t smem_u32(const void* p) {
    uint32_t a;
    asm("{ .reg .u64 t; cvta.to.shared.u64 t, %1; cvt.u32.u64 %0, t; }" : "=r"(a) : "l"(p));
    return a;
}

// Byte offset of half element (r, k) in a swizzled [rows x 256] fp16 tile.
static __device__ __forceinline__ uint32_t swz(uint32_t r, uint32_t k) {
    return r * ROW_BYTES + (((k >> 3) ^ (r & 7)) << 4) + ((k & 7) << 1);
}

static __device__ __forceinline__ void ldsm4(uint32_t r[4], uint32_t addr) {
    asm volatile("ldmatrix.sync.aligned.m8n8.x4.shared.b16 {%0,%1,%2,%3}, [%4];"
                 : "=r"(r[0]), "=r"(r[1]), "=r"(r[2]), "=r"(r[3]) : "r"(addr));
}

static __device__ __forceinline__ void mma16816(float d[4], const uint32_t a[4],
                                                uint32_t b0, uint32_t b1) {
    asm volatile("mma.sync.aligned.m16n8k16.row.col.f32.f16.f16.f32 "
                 "{%0,%1,%2,%3}, {%4,%5,%6,%7}, {%8,%9}, {%0,%1,%2,%3};"
                 : "+f"(d[0]), "+f"(d[1]), "+f"(d[2]), "+f"(d[3])
                 : "r"(a[0]), "r"(a[1]), "r"(a[2]), "r"(a[3]), "r"(b0), "r"(b1));
}

// Packed fp16x2 tanh: one MUFU per value-pair (interior iterations only).
static __device__ __forceinline__ uint32_t tanh_h2(uint32_t h2) {
    uint32_t y;
    asm("tanh.approx.f16x2 %0, %1;" : "=r"(y) : "r"(h2));
    return y;
}

// Accurate final-iteration tanh: 1 - 2/(1 + e^{2x}), ~1e-6 rel error.
static __device__ __forceinline__ float tanh_acc(float x) {
    float e, r;
    asm("ex2.approx.f32 %0, %1;" : "=f"(e) : "f"(x * 2.8853900817779268f));
    asm("rcp.approx.f32 %0, %1;" : "=f"(r) : "f"(1.0f + e));
    return 1.0f - 2.0f * r;
}

// Interior epilogue: cvt fp32->half2, packed tanh, STS into z buffer (n16 slice).
static __device__ __forceinline__ void epi_store(
    char* smem, uint32_t zoff, const float v[2][4], int qr, int wn, int qc)
{
#pragma unroll
    for (int nf = 0; nf < 2; ++nf) {
        int c0 = wn + nf * 8 + qc;
        __half2 h0 = __floats2half2_rn(v[nf][0], v[nf][1]);
        __half2 h1 = __floats2half2_rn(v[nf][2], v[nf][3]);
        uint32_t t0 = tanh_h2(*reinterpret_cast<uint32_t*>(&h0));
        uint32_t t1 = tanh_h2(*reinterpret_cast<uint32_t*>(&h1));
        *reinterpret_cast<uint32_t*>(smem + zoff + swz(qr,     c0)) = t0;
        *reinterpret_cast<uint32_t*>(smem + zoff + swz(qr + 8, c0)) = t1;
    }
}

__global__ void __launch_bounds__(THREADS, 1)
fixed_point_kernel(const float* __restrict__ x, const float* __restrict__ W,
                   const float* __restrict__ b, float* __restrict__ out)
{
    extern __shared__ char smem[];
    const uint32_t sb = smem_u32(smem);
    const uint32_t Wb = sb;

    const int tid = threadIdx.x;
    const int wid = tid >> 5;
    const int l   = tid & 31;
    const int wn  = wid << 4;                 // this warp's 16-col slice of N=256
    const int qr  = l >> 2;
    const int qc  = (l & 3) << 1;

    // ---- One-time: W -> SMEM fp16 swizzled [n][k] ----
    for (int idx = tid; idx < FDIM * (FDIM / 4); idx += THREADS) {
        int n  = idx >> 6;
        int k4 = (idx & 63) << 2;
        float4 wv = *reinterpret_cast<const float4*>(W + n * FDIM + k4);
        __half2 h0 = __floats2half2_rn(wv.x, wv.y);
        __half2 h1 = __floats2half2_rn(wv.z, wv.w);
        uint2 v;
        v.x = *reinterpret_cast<uint32_t*>(&h0);
        v.y = *reinterpret_cast<uint32_t*>(&h1);
        *reinterpret_cast<uint2*>(smem + swz(n, k4)) = v;
    }
    __syncthreads();

    // ---- One-time: B fragments (whole K for this warp's n16 slice) -> 64 regs ----
    const uint32_t b_r = (uint32_t)(wn + ((l >> 4) & 1) * 8 + (l & 7));
    const uint32_t b_k = (uint32_t)(((l >> 3) & 1) * 8);
    uint32_t Breg[64];
#pragma unroll
    for (int ks = 0; ks < 16; ++ks)
        ldsm4(&Breg[ks * 4], Wb + swz(b_r, ks * 16 + b_k));

    // ---- One-time: bias values for this thread's output columns ----
    float bias[2][2];
#pragma unroll
    for (int nf = 0; nf < 2; ++nf) {
        float2 bv = *reinterpret_cast<const float2*>(b + wn + nf * 8 + qc);
        bias[nf][0] = bv.x;
        bias[nf][1] = bv.y;
    }

    const uint32_t a_r = (uint32_t)(((l >> 3) & 1) * 8 + (l & 7));
    const uint32_t a_k = (uint32_t)(((l >> 4) & 1) * 8);
    const uint32_t ZA0 = sb + OFF_ZA0, ZA1 = sb + OFF_ZA1;
    const uint32_t ZB0 = sb + OFF_ZB0, ZB1 = sb + OFF_ZB1;

    // ---- Persistent loop over 32-row tile pairs ----
    for (int pair = blockIdx.x; pair < N_PAIRS; pair += gridDim.x) {
        const int row0 = pair * 32;           // tile A rows [row0,row0+16), B next 16

        // c = x + b fragments for both 16-row tiles
        float cA[2][4], cB[2][4];
#pragma unroll
        for (int half = 0; half < 2; ++half) {
            int rA = row0 + qr + half * 8;
            const float* xrA = x + (size_t)rA * FDIM;
            const float* xrB = xrA + 16 * FDIM;
#pragma unroll
            for (int nf = 0; nf < 2; ++nf) {
                int c0 = wn + nf * 8 + qc;
                float2 xa = *reinterpret_cast<const float2*>(xrA + c0);
                float2 xb = *reinterpret_cast<const float2*>(xrB + c0);
                cA[nf][half * 2 + 0] = xa.x + bias[nf][0];
                cA[nf][half * 2 + 1] = xa.y + bias[nf][1];
                cB[nf][half * 2 + 0] = xb.x + bias[nf][0];
                cB[nf][half * 2 + 1] = xb.y + bias[nf][1];
            }
        }

        // Iteration 0: z1 = tanh(c) -> ping buffers
        epi_store(smem, OFF_ZA0, cA, qr, wn, qc);
        epi_store(smem, OFF_ZB0, cB, qr, wn, qc);
        __syncthreads();

        // Iterations 1..23 (ping-pong z buffers, ONE barrier per iteration)
        float acc[2][4];
        uint32_t abuf[2][4];
#pragma unroll 1
        for (int it = 1; it < N_GEMM; ++it) {
            const bool odd = (it & 1) != 0;
            const uint32_t ZAsrc = odd ? ZA0 : ZA1;
            const uint32_t ZBsrc = odd ? ZB0 : ZB1;
            const uint32_t zAdst = odd ? OFF_ZA1 : OFF_ZA0;
            const uint32_t zBdst = odd ? OFF_ZB1 : OFF_ZB0;

            // ---- tile A GEMM (software-pipelined A ldsm) ----
#pragma unroll
            for (int nf = 0; nf < 2; ++nf)
#pragma unroll
                for (int j = 0; j < 4; ++j)
                    acc[nf][j] = cA[nf][j];
            ldsm4(abuf[0], ZAsrc + swz(a_r, a_k));
#pragma unroll
            for (int ks = 0; ks < 16; ++ks) {
                if (ks < 15)
                    ldsm4(abuf[(ks + 1) & 1], ZAsrc + swz(a_r, (ks + 1) * 16 + a_k));
                const uint32_t* Bk = &Breg[ks * 4];
                mma16816(acc[0], abuf[ks & 1], Bk[0], Bk[1]);
                mma16816(acc[1], abuf[ks & 1], Bk[2], Bk[3]);
            }
            // prefetch tile B's first A-frag; its LDS latency hides under epi A
            ldsm4(abuf[0], ZBsrc + swz(a_r, a_k));
            epi_store(smem, zAdst, acc, qr, wn, qc);

            // ---- tile B GEMM ----
#pragma unroll
            for (int nf = 0; nf < 2; ++nf)
#pragma unroll
                for (int j = 0; j < 4; ++j)
                    acc[nf][j] = cB[nf][j];
#pragma unroll
            for (int ks = 0; ks < 16; ++ks) {
                if (ks < 15)
                    ldsm4(abuf[(ks + 1) & 1], ZBsrc + swz(a_r, (ks + 1) * 16 + a_k));
                const uint32_t* Bk = &Breg[ks * 4];
                mma16816(acc[0], abuf[ks & 1], Bk[0], Bk[1]);
                mma16816(acc[1], abuf[ks & 1], Bk[2], Bk[3]);
            }
            epi_store(smem, zBdst, acc, qr, wn, qc);
            __syncthreads();
        }

        // ---- Final iteration (it = 24, sources are pong buffers ZA1/ZB1) ----
#pragma unroll
        for (int nf = 0; nf < 2; ++nf)
#pragma unroll
            for (int j = 0; j < 4; ++j)
                acc[nf][j] = cA[nf][j];
        ldsm4(abuf[0], ZA1 + swz(a_r, a_k));
#pragma unroll
        for (int ks = 0; ks < 16; ++ks) {
            if (ks < 15)
                ldsm4(abuf[(ks + 1) & 1], ZA1 + swz(a_r, (ks + 1) * 16 + a_k));
            const uint32_t* Bk = &Breg[ks * 4];
            mma16816(acc[0], abuf[ks & 1], Bk[0], Bk[1]);
            mma16816(acc[1], abuf[ks & 1], Bk[2], Bk[3]);
        }
#pragma unroll
        for (int nf = 0; nf < 2; ++nf) {
            int rg = row0 + qr;
            int c0 = wn + nf * 8 + qc;
            float2 v0 = make_float2(tanh_acc(acc[nf][0]), tanh_acc(acc[nf][1]));
            float2 v1 = make_float2(tanh_acc(acc[nf][2]), tanh_acc(acc[nf][3]));
            *reinterpret_cast<float2*>(out + (size_t)rg * FDIM + c0)       = v0;
            *reinterpret_cast<float2*>(out + (size_t)(rg + 8) * FDIM + c0) = v1;
        }

#pragma unroll
        for (int nf = 0; nf < 2; ++nf)
#pragma unroll
            for (int j = 0; j < 4; ++j)
                acc[nf][j] = cB[nf][j];
        ldsm4(abuf[0], ZB1 + swz(a_r, a_k));
#pragma unroll
        for (int ks = 0; ks < 16; ++ks) {
            if (ks < 15)
                ldsm4(abuf[(ks + 1) & 1], ZB1 + swz(a_r, (ks + 1) * 16 + a_k));
            const uint32_t* Bk = &Breg[ks * 4];
            mma16816(acc[0], abuf[ks & 1], Bk[0], Bk[1]);
            mma16816(acc[1], abuf[ks & 1], Bk[2], Bk[3]);
        }
#pragma unroll
        for (int nf = 0; nf < 2; ++nf) {
            int rg = row0 + 16 + qr;
            int c0 = wn + nf * 8 + qc;
            float2 v0 = make_float2(tanh_acc(acc[nf][0]), tanh_acc(acc[nf][1]));
            float2 v1 = make_float2(tanh_acc(acc[nf][2]), tanh_acc(acc[nf][3]));
            *reinterpret_cast<float2*>(out + (size_t)rg * FDIM + c0)       = v0;
            *reinterpret_cast<float2*>(out + (size_t)(rg + 8) * FDIM + c0) = v1;
        }
        __syncthreads();   // z buffers safe for next pair's iteration 0
    }
}

extern "C" void kernel_launch(void* const* d_in, const int* in_sizes, int n_in,
                              void* d_out, int out_size)
{
    (void)in_sizes; (void)n_in; (void)out_size;
    const float* x = (const float*)d_in[0];
    const float* W = (const float*)d_in[1];
    const float* b = (const float*)d_in[2];
    float* out = (float*)d_out;

    int dev = 0, sms = 0;
    cudaGetDevice(&dev);
    cudaDeviceGetAttribute(&sms, cudaDevAttrMultiProcessorCount, dev);
    int grid = sms > 0 ? sms : 128;
    if (grid > N_PAIRS) grid = N_PAIRS;

    cudaFuncSetAttribute(fixed_point_kernel, cudaFuncAttributeMaxDynamicSharedMemorySize, SMEM_BYTES);
    fixed_point_kernel<<<grid, THREADS, SMEM_BYTES>>>(x, W, b, out);
}